// round 8
// baseline (speedup 1.0000x reference)
#include <cuda_runtime.h>

// CTC forward loss. B=32, T=1000, V=1024, L=100, S=2L+1=201.
//
// Pass 1 (parallel): g_emit[b][t][s] = log2(pred[b][t][ext[s]] + EPS)
// Pass 2 (serial DP): BARRIER-FREE warp-skewed pipeline.
//   - alpha register-resident, s-1/s-2 via shfl_up
//   - cross-warp boundary via lock-free tagged 128-bit smem slots
//     (ring of 256/warp; __syncthreads every 128 steps bounds skew < ring)
//   - base-2 log domain (ex2/lg2 approx), emissions precomputed in log2
//   - mean reduce fused via last-block atomicInc pattern
//
#define Bc 32
#define Tc 1000
#define Vc 1024
#define Lc 100
#define Sc 201
#define NEGV (-1e9f)
#define EPSV (1e-7f)
#define NTHREADS 224          // 7 warps, lane-per-thread
#define ESTR 224
#define RING 256              // boundary ring slots per warp (power of 2)
#define LN2F 0.6931471805599453f

__device__ float    g_emit[(size_t)Bc * Tc * ESTR];  // ~28.7 MB scratch
__device__ float    g_loss[Bc];
__device__ unsigned g_done;                          // zero-init; self-resets (atomicInc wrap)

__device__ __forceinline__ float ex2f_(float x) { float y; asm("ex2.approx.ftz.f32 %0, %1;" : "=f"(y) : "f"(x)); return y; }
__device__ __forceinline__ float lg2f_(float x) { float y; asm("lg2.approx.ftz.f32 %0, %1;" : "=f"(y) : "f"(x)); return y; }

__device__ __forceinline__ void st128v(unsigned addr, unsigned x, unsigned y, unsigned z, unsigned w) {
    asm volatile("st.volatile.shared.v4.b32 [%0], {%1,%2,%3,%4};"
                 :: "r"(addr), "r"(x), "r"(y), "r"(z), "r"(w));
}
__device__ __forceinline__ uint4 ld128v(unsigned addr) {
    uint4 v;
    asm volatile("ld.volatile.shared.v4.b32 {%0,%1,%2,%3}, [%4];"
                 : "=r"(v.x), "=r"(v.y), "=r"(v.z), "=r"(v.w) : "r"(addr));
    return v;
}

// ---------------- Pass 1: emission gather + log2 (parallel) ----------------
__global__ __launch_bounds__(NTHREADS)
void ctc_emit_kernel(const float* __restrict__ pred,
                     const int*   __restrict__ lenA,
                     const int*   __restrict__ lenB,
                     const int*   __restrict__ labels)
{
    const int t = blockIdx.x;
    const int b = blockIdx.y;
    const int s = threadIdx.x;

    const int ilen = min(max(max(lenA[b], lenB[b]), 1), Tc);
    if (t >= ilen) return;

    int ext = Vc - 1;
    if ((s & 1) && s < Sc) ext = labels[b * Lc + (s >> 1)] & (Vc - 1);

    const float p = pred[((size_t)b * Tc + t) * Vc + ext];
    g_emit[((size_t)b * Tc + t) * ESTR + s] = lg2f_(p + EPSV);
}

// ---------------- Pass 2: barrier-free serial DP ----------------
__global__ __launch_bounds__(NTHREADS, 1)
void ctc_dp_kernel(const int* __restrict__ lenA,
                   const int* __restrict__ lenB,
                   const int* __restrict__ labels,
                   float*     __restrict__ out)
{
    __shared__ uint4 slots[6 * RING];       // boundary slots for warps 0..5
    __shared__ float afin[NTHREADS];

    const int b    = blockIdx.x;
    const int s    = threadIdx.x;
    const int w    = s >> 5;
    const int lane = s & 31;

    const unsigned slots_base = (unsigned)__cvta_generic_to_shared(slots);
    const unsigned my_pub  = slots_base + (unsigned)(w * RING) * 16u;        // + (t&255)*16
    const unsigned my_sub  = slots_base + (unsigned)((w - 1) * RING) * 16u;  // w>=1 only

    const int la = lenA[b], lb = lenB[b];
    const int ilen = min(max(max(la, lb), 1), Tc);
    const int llen = min(max(min(la, lb), 1), Lc);

    const bool active = (s < Sc);
    const bool valid  = active && (s < 2 * llen + 1);
    bool allow = false;
    if (active && (s & 1)) {
        const int e0 = labels[b * Lc + (s >> 1)] & (Vc - 1);
        allow = (s < 2) ? true : (e0 != (labels[b * Lc + (s >> 1) - 1] & (Vc - 1)));
    }

    const float* eb = g_emit + (size_t)b * Tc * ESTR + s;

    // init tags to sentinel (re-done every launch; graph-replay safe)
    for (int i = s; i < 6 * RING; i += NTHREADS) slots[i].z = 0xFFFFFFFFu;
    __syncthreads();

    // ---- t = 0 ----
    float cura = (valid && s < 2) ? eb[0] : NEGV;

    {   // publish step-0 boundary
        const float v30 = __shfl_sync(0xffffffffu, cura, 30);
        if (lane == 31 && w < 6)
            st128v(my_pub + 0u * 16u, __float_as_uint(v30), __float_as_uint(cura), 0u, 0u);
    }

    // ---- preload log2-emissions for t = 1..8 ----
    float er[8];
    #pragma unroll
    for (int j = 0; j < 8; ++j) {
        int tn = 1 + j; if (tn > Tc - 1) tn = Tc - 1;
        er[j] = eb[(size_t)tn * ESTR];
    }

    int t = 1;
    while (t + 8 <= ilen) {
        #pragma unroll
        for (int j = 0; j < 8; ++j) {
            const int tt = t + j;

            // prefetch emission for step tt+8
            int tn = tt + 8; if (tn > Tc - 1) tn = Tc - 1;
            const float pn = eb[(size_t)tn * ESTR];
            const float el = er[j];

            float am1 = __shfl_up_sync(0xffffffffu, cura, 1);
            float am2 = __shfl_up_sync(0xffffffffu, cura, 2);
            if (lane < 2) {
                if (w > 0) {
                    const unsigned a = my_sub + (unsigned)((tt - 1) & (RING - 1)) * 16u;
                    uint4 v;
                    do { v = ld128v(a); } while (v.z != (unsigned)(tt - 1));
                    const float b30 = __uint_as_float(v.x);
                    const float b31 = __uint_as_float(v.y);
                    if (lane == 0) { am1 = b31; am2 = b30; } else { am2 = b31; }
                } else {
                    if (lane == 0) am1 = NEGV;
                    am2 = NEGV;
                }
            }

            const float cc  = allow ? am2 : NEGV;
            const float m   = fmaxf(cura, fmaxf(am1, cc));
            const float sum = ex2f_(cura - m) + ex2f_(am1 - m) + ex2f_(cc - m);
            const float nv  = m + lg2f_(sum) + el;
            cura = valid ? nv : NEGV;

            const float v30 = __shfl_sync(0xffffffffu, cura, 30);
            if (lane == 31 && w < 6)
                st128v(my_pub + (unsigned)(tt & (RING - 1)) * 16u,
                       __float_as_uint(v30), __float_as_uint(cura), (unsigned)tt, 0u);

            er[j] = pn;
        }
        t += 8;
        // bound warp skew below RING (ring-overwrite guard)
        if (((t - 1) & 127) == 0) __syncthreads();
    }

    // ---- tail (< 8 steps) ----
    for (int j = 0; t < ilen; ++t, ++j) {
        const int tt = t;
        const float el = er[j];

        float am1 = __shfl_up_sync(0xffffffffu, cura, 1);
        float am2 = __shfl_up_sync(0xffffffffu, cura, 2);
        if (lane < 2) {
            if (w > 0) {
                const unsigned a = my_sub + (unsigned)((tt - 1) & (RING - 1)) * 16u;
                uint4 v;
                do { v = ld128v(a); } while (v.z != (unsigned)(tt - 1));
                const float b30 = __uint_as_float(v.x);
                const float b31 = __uint_as_float(v.y);
                if (lane == 0) { am1 = b31; am2 = b30; } else { am2 = b31; }
            } else {
                if (lane == 0) am1 = NEGV;
                am2 = NEGV;
            }
        }

        const float cc  = allow ? am2 : NEGV;
        const float m   = fmaxf(cura, fmaxf(am1, cc));
        const float sum = ex2f_(cura - m) + ex2f_(am1 - m) + ex2f_(cc - m);
        const float nv  = m + lg2f_(sum) + el;
        cura = valid ? nv : NEGV;

        const float v30 = __shfl_sync(0xffffffffu, cura, 30);
        if (lane == 31 && w < 6)
            st128v(my_pub + (unsigned)(tt & (RING - 1)) * 16u,
                   __float_as_uint(v30), __float_as_uint(cura), (unsigned)tt, 0u);
    }

    // ---- finalize: loglik = log2add(a[2l-1], a[2l]) * ln2 ----
    afin[s] = cura;
    __syncthreads();
    if (s == 0) {
        const float a1 = afin[2 * llen - 1];
        const float a2 = afin[2 * llen];
        const float m  = fmaxf(a1, a2);
        const float l2 = m + lg2f_(ex2f_(a1 - m) + ex2f_(a2 - m));
        g_loss[b] = -(l2 * LN2F);

        __threadfence();
        const unsigned old = atomicInc(&g_done, Bc - 1);   // wraps to 0 each launch
        if (old == Bc - 1) {
            __threadfence();
            float acc = 0.0f;
            #pragma unroll
            for (int i = 0; i < Bc; ++i) acc += g_loss[i];
            out[0] = acc * (1.0f / (float)Bc);
        }
    }
}

extern "C" void kernel_launch(void* const* d_in, const int* in_sizes, int n_in,
                              void* d_out, int out_size)
{
    // Identify inputs by size rank (robust to ordering / bytes-vs-elems).
    int idx[4] = {0, 1, 2, 3};
    for (int i = 0; i < 3; ++i)
        for (int j = i + 1; j < 4; ++j)
            if ((long long)in_sizes[idx[j]] > (long long)in_sizes[idx[i]]) {
                int tmp = idx[i]; idx[i] = idx[j]; idx[j] = tmp;
            }

    const float* pred   = (const float*)d_in[idx[0]];  // [B,T,V]
    const int*   labels = (const int*)  d_in[idx[1]];  // [B,L]
    const int*   lenA   = (const int*)  d_in[idx[2]];  // length vectors
    const int*   lenB   = (const int*)  d_in[idx[3]];

    float* out = (float*)d_out;

    dim3 g1(Tc, Bc);
    ctc_emit_kernel<<<g1, NTHREADS>>>(pred, lenA, lenB, labels);
    ctc_dp_kernel<<<Bc, NTHREADS>>>(lenA, lenB, labels, out);
}

// round 10
// speedup vs baseline: 5.3417x; 5.3417x over previous
#include <cuda_runtime.h>

// CTC forward loss. B=32, T=1000, V=1024, L=100, S=2L+1=201.
//
// Pass 1 (parallel): g_emit[b][t][s] = pred[b][t][ext[s]] + EPS  (linear prob;
//   0 for invalid lanes -> DP needs no masking).
// Pass 2 (serial DP): barrier-per-step LINEAR-domain recursion:
//   nv = (a + b + allow*c) * e   -- IEEE FADD/FMA/FMUL (denormal-preserving),
//   exact power-of-2 rescale every 4 steps, target 2^100 (R9 post-mortem:
//   8-step/2^64/FTZ retained only ~76 nats of lane spread -> 2.9e-3 error;
//   this config retains ~140+ nats). Mean-reduce fused.

#define Bc 32
#define Tc 1000
#define Vc 1024
#define Lc 100
#define Sc 201
#define EPSV (1e-7f)
#define NTHREADS 224
#define APAD (NTHREADS + 8)
#define ESTR 224
#define LN2F 0.6931471805599453f

__device__ float    g_emit[(size_t)Bc * Tc * ESTR];   // ~28.7 MB scratch
__device__ float    g_loss[Bc];
__device__ unsigned g_done;                           // zero-init; atomicInc wraps -> reusable

__device__ __forceinline__ float lg2f_(float x) { float y; asm("lg2.approx.ftz.f32 %0, %1;" : "=f"(y) : "f"(x)); return y; }

// ---------------- Pass 1: emission gather (parallel, linear) ----------------
__global__ __launch_bounds__(NTHREADS)
void ctc_emit_kernel(const float* __restrict__ pred,
                     const int*   __restrict__ lenA,
                     const int*   __restrict__ lenB,
                     const int*   __restrict__ labels)
{
    const int t = blockIdx.x;
    const int b = blockIdx.y;
    const int s = threadIdx.x;

    const int la = lenA[b], lb = lenB[b];
    const int ilen = min(max(max(la, lb), 1), Tc);
    const int llen = min(max(min(la, lb), 1), Lc);
    if (t >= ilen) return;                       // DP never consumes t >= ilen

    int ext = Vc - 1;                            // blank
    if ((s & 1) && s < Sc) ext = labels[b * Lc + (s >> 1)] & (Vc - 1);

    const bool valid = (s < Sc) && (s < 2 * llen + 1);
    const float p = pred[((size_t)b * Tc + t) * Vc + ext];
    g_emit[((size_t)b * Tc + t) * ESTR + s] = valid ? (p + EPSV) : 0.0f;
}

// ---------------- Pass 2: serial DP (linear domain) ----------------
__global__ __launch_bounds__(NTHREADS, 1)
void ctc_dp_kernel(const int* __restrict__ lenA,
                   const int* __restrict__ lenB,
                   const int* __restrict__ labels,
                   float*     __restrict__ out)
{
    __shared__ float alpha[2][APAD];   // lane s at [s+2]; [0..1] = zero pad
    __shared__ float red[7];

    const int b = blockIdx.x;
    const int s = threadIdx.x;

    const int la = lenA[b], lb = lenB[b];
    const int ilen = min(max(max(la, lb), 1), Tc);
    const int llen = min(max(min(la, lb), 1), Lc);

    const bool active = (s < Sc);
    float allowf = 0.0f;
    if (active && (s & 1)) {
        const int e0 = labels[b * Lc + (s >> 1)] & (Vc - 1);
        allowf = (s < 2) ? 1.0f
               : ((e0 != (labels[b * Lc + (s >> 1) - 1] & (Vc - 1))) ? 1.0f : 0.0f);
    }

    const float* eb = g_emit + (size_t)b * Tc * ESTR + s;

    // zero both buffers (full padded range)
    alpha[0][s] = 0.0f;  alpha[1][s] = 0.0f;
    if (s < APAD - NTHREADS) {
        alpha[0][NTHREADS + s] = 0.0f;
        alpha[1][NTHREADS + s] = 0.0f;
    }
    __syncthreads();

    // ---- t = 0 : lanes 0,1 get emission (emit already zeroed invalid lanes)
    alpha[0][s + 2] = (s < 2) ? eb[0] : 0.0f;

    // ---- preload emissions for t = 1..8 ----
    float er[8];
    #pragma unroll
    for (int j = 0; j < 8; ++j) {
        int tn = 1 + j; if (tn > Tc - 1) tn = Tc - 1;
        er[j] = eb[(size_t)tn * ESTR];
    }
    __syncthreads();

    int   cur = 0;
    int   t   = 1;
    int   Ktot = 0;                       // accumulated log2 of inverse total scale
    float pend1 = 1.0f, pend2 = 1.0f;     // deferred exact 2^k rescale

    // ---- full 8-step windows; rescale every 4 steps ----
    while (t + 8 <= ilen) {
        #pragma unroll
        for (int j = 0; j < 8; ++j) {
            // prefetch emission for step t+8+j
            int tn = t + 8 + j; if (tn > Tc - 1) tn = Tc - 1;
            const float pn = eb[(size_t)tn * ESTR];

            const float a  = alpha[cur][s + 2];
            const float bb = alpha[cur][s + 1];
            const float cc = alpha[cur][s];

            // IEEE (non-FTZ) chain: denormals preserved even under fast-math.
            float nv = __fmul_rn(__fmaf_rn(allowf, cc, __fadd_rn(a, bb)), er[j]);
            if (j == 0 || j == 4) nv = __fmul_rn(__fmul_rn(nv, pend1), pend2);

            alpha[cur ^ 1][s + 2] = nv;

            if (j == 3 || j == 7) {   // block max (nv >= 0: uint order == float order)
                const unsigned mm = __reduce_max_sync(0xffffffffu, __float_as_uint(nv));
                if ((threadIdx.x & 31) == 0) red[threadIdx.x >> 5] = __uint_as_float(mm);
            }
            __syncthreads();

            if (j == 3 || j == 7) {
                float m = red[0];
                #pragma unroll
                for (int ww = 1; ww < 7; ++ww) m = fmaxf(m, red[ww]);
                const int ee = (int)((__float_as_uint(m) >> 23) & 0xFF);  // biased exp
                const int k  = 227 - ee;                                  // scale = 2^k, target 2^100
                const int k1 = k >> 1, k2 = k - k1;
                pend1 = __uint_as_float((unsigned)(127 + k1) << 23);
                pend2 = __uint_as_float((unsigned)(127 + k2) << 23);
                Ktot += k;
            }

            cur ^= 1;
            er[j] = pn;
        }
        t += 8;
    }

    // ---- tail (< 8 steps); emissions resident in er[] ----
    for (int j = 0; t < ilen; ++t, ++j) {
        const float a  = alpha[cur][s + 2];
        const float bb = alpha[cur][s + 1];
        const float cc = alpha[cur][s];

        float nv = __fmul_rn(__fmaf_rn(allowf, cc, __fadd_rn(a, bb)), er[j]);
        if (j == 0) { nv = __fmul_rn(__fmul_rn(nv, pend1), pend2); pend1 = 1.0f; pend2 = 1.0f; }

        alpha[cur ^ 1][s + 2] = nv;
        __syncthreads();
        cur ^= 1;
    }

    // ---- finalize: loglik = (log2(a1+a2) - Ktot) * ln2 ----
    if (s == 0) {
        const float a1 = alpha[cur][2 * llen - 1 + 2];
        const float a2 = alpha[cur][2 * llen + 2];
        const float sum = __fmul_rn(__fmul_rn(__fadd_rn(a1, a2), pend1), pend2);
        const float ll  = (lg2f_(sum) - (float)Ktot) * LN2F;
        g_loss[b] = -ll;

        __threadfence();
        const unsigned old = atomicInc(&g_done, Bc - 1);   // wraps to 0 each launch
        if (old == Bc - 1) {
            __threadfence();
            float acc = 0.0f;
            #pragma unroll
            for (int i = 0; i < Bc; ++i) acc += g_loss[i];
            out[0] = acc * (1.0f / (float)Bc);
        }
    }
}

extern "C" void kernel_launch(void* const* d_in, const int* in_sizes, int n_in,
                              void* d_out, int out_size)
{
    // Identify inputs by size rank (robust to ordering / bytes-vs-elems).
    int idx[4] = {0, 1, 2, 3};
    for (int i = 0; i < 3; ++i)
        for (int j = i + 1; j < 4; ++j)
            if ((long long)in_sizes[idx[j]] > (long long)in_sizes[idx[i]]) {
                int tmp = idx[i]; idx[i] = idx[j]; idx[j] = tmp;
            }

    const float* pred   = (const float*)d_in[idx[0]];  // [B,T,V]
    const int*   labels = (const int*)  d_in[idx[1]];  // [B,L]
    const int*   lenA   = (const int*)  d_in[idx[2]];  // length vectors
    const int*   lenB   = (const int*)  d_in[idx[3]];

    float* out = (float*)d_out;

    dim3 g1(Tc, Bc);
    ctc_emit_kernel<<<g1, NTHREADS>>>(pred, lenA, lenB, labels);
    ctc_dp_kernel<<<Bc, NTHREADS>>>(lenA, lenB, labels, out);
}